// round 7
// baseline (speedup 1.0000x reference)
#include <cuda_runtime.h>
#include <cuda_bf16.h>
#include <math.h>

// Problem constants (fixed by the reference's setup_inputs)
#define BATCH 2
#define NQ 12240
#define EMB 256
#define NHEAD 8
#define HDIM 32
#define NLVL 4
#define NPTS 4
#define VLEN 12240          // 96*96 + 48*48 + 24*24 + 12*12
#define MROWS (BATCH * NQ)  // 24480 (also BATCH*VLEN)
#define PCOLS 384           // 256 offset cols + 128 attn cols

// Scratch (no cudaMalloc allowed)
__device__ float g_V[BATCH * VLEN * EMB];   // projected value, (B, Vlen, E)
__device__ float g_P[MROWS * PCOLS];        // raw proj: [0:256) offsets, [256:384) attn logits
__device__ float g_T[MROWS * EMB];          // accumulated per-query features

// ---------------------------------------------------------------------------
// fp32 tiled GEMM: C[M,N] = A[M,K] @ W[K,N] (+ bias), A row-major (ld=K),
// W row-major (ld=N), C row-major with ldc.
// BM=128, BN=64, BK=16, 256 threads, 8x4 microtile per thread.
// 2-stage software pipeline on the global loads.
// ---------------------------------------------------------------------------
#define BM 128
#define BN 64
#define BK 16

__global__ __launch_bounds__(256)
void gemm_kernel(const float* __restrict__ A, const float* __restrict__ W,
                 const float* __restrict__ bias, float* __restrict__ C,
                 int M, int N, int K, int ldc) {
    __shared__ float As[BK][BM + 1];
    __shared__ float Bs[BK][BN];

    const int tid  = threadIdx.x;
    const int row0 = blockIdx.y * BM;
    const int col0 = blockIdx.x * BN;
    const int tm   = tid >> 4;      // 0..15 -> 8 rows each
    const int tn   = tid & 15;      // 0..15 -> 4 cols each

    // A tile: 128x16 floats = 512 float4; 2 float4 per thread (rows r, r+64)
    const int arow = tid >> 2;           // 0..63
    const int ak   = (tid & 3) * 4;      // 0,4,8,12
    // W tile: 16x64 floats = 256 float4; 1 per thread
    const int brow = tid >> 4;           // 0..15
    const int bcol = (tid & 15) * 4;     // 0..60

    const bool a0ok = (row0 + arow) < M;
    const bool a1ok = (row0 + arow + 64) < M;
    const float* Ap0 = &A[(long)(row0 + arow) * K + ak];
    const float* Ap1 = &A[(long)(row0 + arow + 64) * K + ak];
    const float* Wp  = &W[(long)brow * N + col0 + bcol];

    float acc[8][4] = {};
    const float4 z4 = make_float4(0.f, 0.f, 0.f, 0.f);

    // prologue: fetch k-tile 0
    float4 av0 = a0ok ? *(const float4*)Ap0 : z4;
    float4 av1 = a1ok ? *(const float4*)Ap1 : z4;
    float4 bv  = *(const float4*)Wp;

    for (int k0 = 0; k0 < K; k0 += BK) {
        // stage current tile into smem
        As[ak + 0][arow] = av0.x;  As[ak + 1][arow] = av0.y;
        As[ak + 2][arow] = av0.z;  As[ak + 3][arow] = av0.w;
        As[ak + 0][arow + 64] = av1.x;  As[ak + 1][arow + 64] = av1.y;
        As[ak + 2][arow + 64] = av1.z;  As[ak + 3][arow + 64] = av1.w;
        *(float4*)&Bs[brow][bcol] = bv;
        __syncthreads();

        // prefetch next tile into registers (overlaps with compute below)
        if (k0 + BK < K) {
            av0 = a0ok ? *(const float4*)(Ap0 + k0 + BK) : z4;
            av1 = a1ok ? *(const float4*)(Ap1 + k0 + BK) : z4;
            bv  = *(const float4*)(Wp + (long)(k0 + BK) * N);
        }

        #pragma unroll
        for (int k = 0; k < BK; k++) {
            float a[8];
            #pragma unroll
            for (int i = 0; i < 8; i++) a[i] = As[k][tm * 8 + i];
            float4 b = *(const float4*)&Bs[k][tn * 4];
            #pragma unroll
            for (int i = 0; i < 8; i++) {
                acc[i][0] += a[i] * b.x;
                acc[i][1] += a[i] * b.y;
                acc[i][2] += a[i] * b.z;
                acc[i][3] += a[i] * b.w;
            }
        }
        __syncthreads();
    }

    #pragma unroll
    for (int i = 0; i < 8; i++) {
        int r = row0 + tm * 8 + i;
        if (r >= M) continue;
        #pragma unroll
        for (int j = 0; j < 4; j++) {
            int c = col0 + tn * 4 + j;
            float v = acc[i][j];
            if (bias) v += bias[c];
            C[(long)r * ldc + c] = v;
        }
    }
}

// ---------------------------------------------------------------------------
// Fused sampling kernel: one warp per (b, q, h).
// - loads raw offset logits (32 per head) -> tanh
// - loads raw attn logits (16 per head) -> in-warp softmax
// - 16 bilinear samples of 32 channels each from g_V (layout B, Vlen, E)
// - writes accumulated 32-channel result into g_T
// ---------------------------------------------------------------------------
__global__ __launch_bounds__(256)
void sample_kernel(const float* __restrict__ ref_points) {
    const int warpId = threadIdx.x >> 5;
    const int lane   = threadIdx.x & 31;
    const long idx   = (long)blockIdx.x * 8 + warpId;       // b*Q*H grid
    const int h   = (int)(idx % NHEAD);
    const long bq = idx / NHEAD;                            // b*Q + q
    const int b   = (int)(bq / NQ);

    const int lvlH[NLVL]   = {96, 48, 24, 12};
    const int lvlW[NLVL]   = {96, 48, 24, 12};
    const int starts[NLVL] = {0, 9216, 11520, 12096};

    const float* Prow = g_P + bq * PCOLS;

    // offsets: tanh of raw logits; lane l holds offset component l of this head
    float off = tanhf(Prow[h * 32 + lane]);

    // attention softmax over 16 logits (lanes 0..15 hold them)
    float araw = (lane < 16) ? Prow[256 + h * 16 + lane] : -1e30f;
    float m = araw;
    #pragma unroll
    for (int s = 16; s; s >>= 1) m = fmaxf(m, __shfl_xor_sync(0xffffffffu, m, s));
    float e = (lane < 16) ? __expf(araw - m) : 0.f;
    float ssum = e;
    #pragma unroll
    for (int s = 16; s; s >>= 1) ssum += __shfl_xor_sync(0xffffffffu, ssum, s);
    float attn = e / ssum;

    const float* Vb   = g_V + (long)b * VLEN * EMB;
    const int    chan = h * HDIM + lane;
    float acc = 0.f;

    #pragma unroll
    for (int l = 0; l < NLVL; l++) {
        const float rx = ref_points[(bq * NLVL + l) * 2 + 0];
        const float ry = ref_points[(bq * NLVL + l) * 2 + 1];
        const int Hl = lvlH[l], Wl = lvlW[l];
        const float* base = Vb + (long)starts[l] * EMB + chan;

        #pragma unroll
        for (int kk = 0; kk < NPTS; kk++) {
            const int j = l * NPTS + kk;
            const float ox = __shfl_sync(0xffffffffu, off, 2 * j + 0);
            const float oy = __shfl_sync(0xffffffffu, off, 2 * j + 1);
            const float a  = __shfl_sync(0xffffffffu, attn, j);

            float x = fminf(fmaxf(rx + ox, -1.f), 1.f);
            float y = fminf(fmaxf(ry + oy, -1.f), 1.f);
            float px = (x + 1.f) * 0.5f * (float)(Wl - 1);
            float py = (y + 1.f) * 0.5f * (float)(Hl - 1);
            float fx = floorf(px), fy = floorf(py);
            float wx = px - fx,   wy = py - fy;
            int x0 = min(max((int)fx, 0), Wl - 1);
            int x1 = min(x0 + 1, Wl - 1);
            int y0 = min(max((int)fy, 0), Hl - 1);
            int y1 = min(y0 + 1, Hl - 1);

            float v00 = base[(long)(y0 * Wl + x0) * EMB];
            float v01 = base[(long)(y0 * Wl + x1) * EMB];
            float v10 = base[(long)(y1 * Wl + x0) * EMB];
            float v11 = base[(long)(y1 * Wl + x1) * EMB];

            float top = v00 + wx * (v01 - v00);
            float bot = v10 + wx * (v11 - v10);
            acc += a * (top + wy * (bot - top));
        }
    }

    g_T[bq * EMB + chan] = acc;
}

extern "C" void kernel_launch(void* const* d_in, const int* in_sizes, int n_in,
                              void* d_out, int out_size) {
    const float* queries    = (const float*)d_in[0];
    const float* ref_points = (const float*)d_in[1];
    const float* value      = (const float*)d_in[2];
    const float* Wv         = (const float*)d_in[3];
    const float* Woff       = (const float*)d_in[4];
    const float* boff       = (const float*)d_in[5];
    const float* Wattn      = (const float*)d_in[6];
    const float* battn      = (const float*)d_in[7];
    const float* Wout       = (const float*)d_in[8];
    float* out = (float*)d_out;

    float *V, *P, *T;
    cudaGetSymbolAddress((void**)&V, g_V);
    cudaGetSymbolAddress((void**)&P, g_P);
    cudaGetSymbolAddress((void**)&T, g_T);

    const int mTiles = (MROWS + BM - 1) / BM;   // 192
    dim3 blk(256);

    // 1) V = value @ Wv        (B*Vlen, 256)
    gemm_kernel<<<dim3(EMB / BN, mTiles), blk>>>(value, Wv, nullptr, V,
                                                 MROWS, EMB, EMB, EMB);
    // 2) P[:, :256] = queries @ Woff + boff
    gemm_kernel<<<dim3(256 / BN, mTiles), blk>>>(queries, Woff, boff, P,
                                                 MROWS, 256, EMB, PCOLS);
    // 3) P[:, 256:384] = queries @ Wattn + battn
    gemm_kernel<<<dim3(128 / BN, mTiles), blk>>>(queries, Wattn, battn, P + 256,
                                                 MROWS, 128, EMB, PCOLS);
    // 4) fused tanh/softmax/bilinear-sample/accumulate -> T
    sample_kernel<<<(BATCH * NQ * NHEAD) / 8, 256>>>(ref_points);
    // 5) out = T @ Wout
    gemm_kernel<<<dim3(EMB / BN, mTiles), blk>>>(T, Wout, nullptr, out,
                                                 MROWS, EMB, EMB, EMB);
}

// round 10
// speedup vs baseline: 1.1167x; 1.1167x over previous
#include <cuda_runtime.h>
#include <cuda_bf16.h>
#include <math.h>

// Problem constants (fixed by the reference's setup_inputs)
#define BATCH 2
#define NQ 12240
#define EMB 256
#define NHEAD 8
#define HDIM 32
#define NLVL 4
#define NPTS 4
#define VLEN 12240          // 96*96 + 48*48 + 24*24 + 12*12
#define MROWS (BATCH * NQ)  // 24480 (also BATCH*VLEN)
#define PCOLS 384           // 256 offset cols + 128 attn cols

// Scratch (no cudaMalloc allowed)
__device__ float g_V[BATCH * VLEN * EMB];   // projected value, (B, Vlen, E)
__device__ float g_P[MROWS * PCOLS];        // raw proj: [0:256) offsets, [256:384) attn logits
__device__ float g_T[MROWS * EMB];          // accumulated per-query features

// ---------------------------------------------------------------------------
// fp32 tiled GEMM: C[M,N] = A[M,K] @ W[K,N] (+ bias), A row-major (ld=K),
// W row-major (ld=N), C row-major with ldc.
// BM=128, BN=64, BK=16, 256 threads, 8x4 microtile per thread.
// 2-stage software pipeline on the global loads.
// ---------------------------------------------------------------------------
#define BM 128
#define BN 64
#define BK 16

__global__ __launch_bounds__(256)
void gemm_kernel(const float* __restrict__ A, const float* __restrict__ W,
                 const float* __restrict__ bias, float* __restrict__ C,
                 int M, int N, int K, int ldc) {
    __shared__ float As[BK][BM + 1];
    __shared__ float Bs[BK][BN];

    const int tid  = threadIdx.x;
    const int row0 = blockIdx.y * BM;
    const int col0 = blockIdx.x * BN;
    const int tm   = tid >> 4;      // 0..15 -> 8 rows each
    const int tn   = tid & 15;      // 0..15 -> 4 cols each

    const int arow = tid >> 2;           // 0..63
    const int ak   = (tid & 3) * 4;      // 0,4,8,12
    const int brow = tid >> 4;           // 0..15
    const int bcol = (tid & 15) * 4;     // 0..60

    const bool a0ok = (row0 + arow) < M;
    const bool a1ok = (row0 + arow + 64) < M;
    const float* Ap0 = &A[(long)(row0 + arow) * K + ak];
    const float* Ap1 = &A[(long)(row0 + arow + 64) * K + ak];
    const float* Wp  = &W[(long)brow * N + col0 + bcol];

    float acc[8][4] = {};
    const float4 z4 = make_float4(0.f, 0.f, 0.f, 0.f);

    float4 av0 = a0ok ? *(const float4*)Ap0 : z4;
    float4 av1 = a1ok ? *(const float4*)Ap1 : z4;
    float4 bv  = *(const float4*)Wp;

    for (int k0 = 0; k0 < K; k0 += BK) {
        As[ak + 0][arow] = av0.x;  As[ak + 1][arow] = av0.y;
        As[ak + 2][arow] = av0.z;  As[ak + 3][arow] = av0.w;
        As[ak + 0][arow + 64] = av1.x;  As[ak + 1][arow + 64] = av1.y;
        As[ak + 2][arow + 64] = av1.z;  As[ak + 3][arow + 64] = av1.w;
        *(float4*)&Bs[brow][bcol] = bv;
        __syncthreads();

        if (k0 + BK < K) {
            av0 = a0ok ? *(const float4*)(Ap0 + k0 + BK) : z4;
            av1 = a1ok ? *(const float4*)(Ap1 + k0 + BK) : z4;
            bv  = *(const float4*)(Wp + (long)(k0 + BK) * N);
        }

        #pragma unroll
        for (int k = 0; k < BK; k++) {
            float a[8];
            #pragma unroll
            for (int i = 0; i < 8; i++) a[i] = As[k][tm * 8 + i];
            float4 b = *(const float4*)&Bs[k][tn * 4];
            #pragma unroll
            for (int i = 0; i < 8; i++) {
                acc[i][0] += a[i] * b.x;
                acc[i][1] += a[i] * b.y;
                acc[i][2] += a[i] * b.z;
                acc[i][3] += a[i] * b.w;
            }
        }
        __syncthreads();
    }

    #pragma unroll
    for (int i = 0; i < 8; i++) {
        int r = row0 + tm * 8 + i;
        if (r >= M) continue;
        #pragma unroll
        for (int j = 0; j < 4; j++) {
            int c = col0 + tn * 4 + j;
            float v = acc[i][j];
            if (bias) v += bias[c];
            C[(long)r * ldc + c] = v;
        }
    }
}

// ---------------------------------------------------------------------------
// Fused sampling kernel v2: one warp per (b, q, h).
// Lane-redundant coordinate math eliminated: lane j (j<16) precomputes point
// j's geometry (base offset, x/y steps, 4 pre-multiplied bilinear*attn
// weights); the main loop broadcasts 7 scalars per point and does 4 coalesced
// gathers + 4 FFMA. All index math 32-bit.
// ---------------------------------------------------------------------------
__device__ __forceinline__ float tanh_approx(float x) {
    float r;
    asm("tanh.approx.f32 %0, %1;" : "=f"(r) : "f"(x));
    return r;
}

__global__ __launch_bounds__(256)
void sample_kernel(const float* __restrict__ ref_points) {
    const int warpId = threadIdx.x >> 5;
    const int lane   = threadIdx.x & 31;
    const int idx    = blockIdx.x * 8 + warpId;   // b*Q*H index (fits int)
    const int h      = idx & (NHEAD - 1);
    const int bq     = idx >> 3;                  // b*Q + q
    const int b      = (bq >= NQ) ? 1 : 0;

    const float* Prow = g_P + bq * PCOLS;

    // offset logits: lane l holds component l of this head's 32 offsets
    float off = tanh_approx(Prow[h * 32 + lane]);

    // attention softmax over 16 logits (lanes 0..15 hold them)
    float araw = (lane < 16) ? Prow[256 + h * 16 + lane] : -1e30f;
    float m = araw;
    #pragma unroll
    for (int s = 16; s; s >>= 1) m = fmaxf(m, __shfl_xor_sync(0xffffffffu, m, s));
    float e = (lane < 16) ? __expf(araw - m) : 0.f;
    float ssum = e;
    #pragma unroll
    for (int s = 16; s; s >>= 1) ssum += __shfl_xor_sync(0xffffffffu, ssum, s);
    float attn = e / ssum;   // lane j (<16): weight of point j

    // ---- per-point geometry, computed once by lane j for point j ----
    // level tables (indexed by l = j>>2; lanes >=16 masked to valid range)
    const int l = (lane >> 2) & 3;
    const int dims[NLVL]   = {96, 48, 24, 12};           // Hl == Wl
    const int starts[NLVL] = {0, 9216, 11520, 12096};
    const int Wl = dims[l];

    const float rx = ref_points[(bq * NLVL + l) * 2 + 0];
    const float ry = ref_points[(bq * NLVL + l) * 2 + 1];
    const float ox = __shfl_sync(0xffffffffu, off, (2 * lane) & 31);
    const float oy = __shfl_sync(0xffffffffu, off, (2 * lane + 1) & 31);

    const float x = fminf(fmaxf(rx + ox, -1.f), 1.f);
    const float y = fminf(fmaxf(ry + oy, -1.f), 1.f);
    const float px = (x + 1.f) * 0.5f * (float)(Wl - 1);
    const float py = (y + 1.f) * 0.5f * (float)(Wl - 1);
    const float fx = floorf(px), fy = floorf(py);
    const float wx = px - fx,   wy = py - fy;
    const int x0 = min(max((int)fx, 0), Wl - 1);
    const int x1 = min(x0 + 1, Wl - 1);
    const int y0 = min(max((int)fy, 0), Wl - 1);
    const int y1 = min(y0 + 1, Wl - 1);

    const int o00 = (starts[l] + y0 * Wl + x0) * EMB;   // element offset, < 3.2M
    const int xs  = (x1 - x0) * EMB;                    // 0 or 256
    const int ys  = (y1 - y0) * Wl * EMB;               // 0 or Wl*256

    const float w00 = attn * (1.f - wx) * (1.f - wy);
    const float w01 = attn * wx * (1.f - wy);
    const float w10 = attn * (1.f - wx) * wy;
    const float w11 = attn * wx * wy;

    // ---- gather + accumulate: 16 points, broadcast geometry per point ----
    const float* Vb = g_V + (size_t)b * (VLEN * EMB) + h * HDIM + lane;
    float acc = 0.f;

    #pragma unroll
    for (int p = 0; p < 16; p++) {
        const int   o   = __shfl_sync(0xffffffffu, o00, p);
        const int   dx  = __shfl_sync(0xffffffffu, xs,  p);
        const int   dy  = __shfl_sync(0xffffffffu, ys,  p);
        const float a00 = __shfl_sync(0xffffffffu, w00, p);
        const float a01 = __shfl_sync(0xffffffffu, w01, p);
        const float a10 = __shfl_sync(0xffffffffu, w10, p);
        const float a11 = __shfl_sync(0xffffffffu, w11, p);

        const float* pb = Vb + o;
        acc += a00 * pb[0] + a01 * pb[dx] + a10 * pb[dy] + a11 * pb[dx + dy];
    }

    g_T[bq * EMB + h * HDIM + lane] = acc;
}

extern "C" void kernel_launch(void* const* d_in, const int* in_sizes, int n_in,
                              void* d_out, int out_size) {
    const float* queries    = (const float*)d_in[0];
    const float* ref_points = (const float*)d_in[1];
    const float* value      = (const float*)d_in[2];
    const float* Wv         = (const float*)d_in[3];
    const float* Woff       = (const float*)d_in[4];
    const float* boff       = (const float*)d_in[5];
    const float* Wattn      = (const float*)d_in[6];
    const float* battn      = (const float*)d_in[7];
    const float* Wout       = (const float*)d_in[8];
    float* out = (float*)d_out;

    float *V, *P, *T;
    cudaGetSymbolAddress((void**)&V, g_V);
    cudaGetSymbolAddress((void**)&P, g_P);
    cudaGetSymbolAddress((void**)&T, g_T);

    const int mTiles = (MROWS + BM - 1) / BM;   // 192
    dim3 blk(256);

    // 1) V = value @ Wv        (B*Vlen, 256)
    gemm_kernel<<<dim3(EMB / BN, mTiles), blk>>>(value, Wv, nullptr, V,
                                                 MROWS, EMB, EMB, EMB);
    // 2) P[:, :256] = queries @ Woff + boff
    gemm_kernel<<<dim3(256 / BN, mTiles), blk>>>(queries, Woff, boff, P,
                                                 MROWS, 256, EMB, PCOLS);
    // 3) P[:, 256:384] = queries @ Wattn + battn
    gemm_kernel<<<dim3(128 / BN, mTiles), blk>>>(queries, Wattn, battn, P + 256,
                                                 MROWS, 128, EMB, PCOLS);
    // 4) fused tanh/softmax/bilinear-sample/accumulate -> T
    sample_kernel<<<(BATCH * NQ * NHEAD) / 8, 256>>>(ref_points);
    // 5) out = T @ Wout
    gemm_kernel<<<dim3(EMB / BN, mTiles), blk>>>(T, Wout, nullptr, out,
                                                 MROWS, EMB, EMB, EMB);
}